// round 2
// baseline (speedup 1.0000x reference)
#include <cuda_runtime.h>

// GruAeModel: B=1024, S=1024, F=36 (12 raw + 4+4+8+8 emb), H=20.
// Round 2: 2 batch elements per warp (shared weight registers, 2x in-warp ILP),
// shuffle-based gate exchange, split accumulation chains, fma.rn.f32x2 math.
// 128 blocks x 4 warps (1 warp/SMSP), 2 elems/warp = 1024 batch elements.

#define HH 20
#define FF 36
#define RR 12
#define BB 1024
#define SS 1024
#define NWARPS 4
#define NTHREADS (NWARPS * 32)

typedef unsigned long long u64;

__device__ __forceinline__ u64 ffma2(u64 a, u64 b, u64 c) {
    u64 d;
    asm("fma.rn.f32x2 %0, %1, %2, %3;" : "=l"(d) : "l"(a), "l"(b), "l"(c));
    return d;
}
__device__ __forceinline__ u64 fadd2(u64 a, u64 b) {
    u64 d;
    asm("add.rn.f32x2 %0, %1, %2;" : "=l"(d) : "l"(a), "l"(b));
    return d;
}
__device__ __forceinline__ float fold2(u64 a) {
    float lo = __uint_as_float((unsigned)a);
    float hi = __uint_as_float((unsigned)(a >> 32));
    return lo + hi;
}
__device__ __forceinline__ float sigf(float x) {
    float e = __expf(-x);
    return __fdividef(1.0f, 1.0f + e);
}
__device__ __forceinline__ float tanhfast(float x) {
    float e = __expf(2.0f * x);
    return 1.0f - __fdividef(2.0f, 1.0f + e);
}

__global__ __launch_bounds__(NTHREADS, 1) void gruae_kernel(
    const float* __restrict__ x, const int* __restrict__ oneh,
    const float* __restrict__ e0t, const float* __restrict__ e1t,
    const float* __restrict__ e2t, const float* __restrict__ e3t,
    const float* __restrict__ Wih1, const float* __restrict__ Whh1,
    const float* __restrict__ bih1, const float* __restrict__ bhh1,
    const float* __restrict__ Wih2, const float* __restrict__ Whh2,
    const float* __restrict__ bih2, const float* __restrict__ bhh2,
    const float* __restrict__ Wfc, const float* __restrict__ bfc,
    float* __restrict__ out) {
    __shared__ __align__(16) float etab[1320];  // e0(40) e1@40 e2@120 e3@520
    __shared__ __align__(16) float XS[NWARPS][2][2][40];  // [warp][parity][elem][F pad]
    __shared__ __align__(16) float HS[NWARPS][2][24];     // [warp][elem][H pad]

    const int tid = threadIdx.x;
    const int wid = tid >> 5;
    const int lane = tid & 31;

    for (int i = tid; i < 40; i += NTHREADS) etab[i] = e0t[i];
    for (int i = tid; i < 80; i += NTHREADS) etab[40 + i] = e1t[i];
    for (int i = tid; i < 400; i += NTHREADS) etab[120 + i] = e2t[i];
    for (int i = tid; i < 800; i += NTHREADS) etab[520 + i] = e3t[i];

    const int b0 = 2 * (blockIdx.x * NWARPS + wid);
    const int b1 = b0 + 1;

    // ---- gate mapping: lane l<20: gA=r_l (row l), gB=z_l (row 20+l)
    //      lane 20+k:    gA=n_k (row 40+k), gB=n_{10+k} (row 50+k)
    const int gA = (lane < 20) ? lane : lane + 20;
    const int gB = (lane < 20) ? lane + 20 : lane + 30;
    const int nsrc = 20 + (lane % 10);     // shfl source for n-gates
    const bool nlo = (lane < 10);          // pick accA vs accB from source

    u64 wiA[18], wiB[18], whA[10], whB[10];
    float biA = 0.f, biB = 0.f, bhA = 0.f, bhB = 0.f;
    if (lane < 30) {
        const u64* ra = (const u64*)(Wih1 + gA * FF);
        const u64* rb = (const u64*)(Wih1 + gB * FF);
#pragma unroll
        for (int j = 0; j < 18; j++) { wiA[j] = ra[j]; wiB[j] = rb[j]; }
        const u64* ha = (const u64*)(Whh1 + gA * HH);
        const u64* hb = (const u64*)(Whh1 + gB * HH);
#pragma unroll
        for (int j = 0; j < 10; j++) { whA[j] = ha[j]; whB[j] = hb[j]; }
        biA = bih1[gA]; biB = bih1[gB]; bhA = bhh1[gA]; bhB = bhh1[gB];
    }

    float hreg0 = 0.f, hreg1 = 0.f;
    if (lane < HH) { HS[wid][0][lane] = 0.f; HS[wid][1][lane] = 0.f; }
    __syncthreads();

    // ---- input streams: lanes 0-15 -> elem0, 16-31 -> elem1; j<12 raw x, j 12..15 onehot
    const int e = lane >> 4;
    const int j16 = lane & 15;
    const int b_e = b0 + e;
    const float* xptr = x + (size_t)b_e * SS * RR + j16;
    const int* optr = oneh + (size_t)b_e * SS * 4 + (j16 - 12);
    float xq0 = 0.f, xq1 = 0.f, xq2 = 0.f;
    int oq0 = 0, oq1 = 0, oq2 = 0;
    if (j16 < 12) {
        xq0 = xptr[0]; xq1 = xptr[12]; xq2 = xptr[24]; xptr += 36;
    } else {
        oq0 = optr[0]; oq1 = optr[4]; oq2 = optr[8]; optr += 12;
    }
    // emb column params (valid for j16 in 12..15)
    const int ec = j16 - 12;
    const int edim = (ec < 2) ? 4 : 8;
    const int eoff = (ec == 0) ? 12 : (ec == 1) ? 16 : (ec == 2) ? 20 : 28;
    const int etb = (ec == 0) ? 0 : (ec == 1) ? 40 : (ec == 2) ? 120 : 520;

    float* origin0 = out + (size_t)b0 * SS * FF;
    float* origin1 = out + (size_t)b1 * SS * FF;
    float* xso0 = out + (size_t)BB * SS * FF + (size_t)b0 * SS * FF;
    float* xso1 = out + (size_t)BB * SS * FF + (size_t)b1 * SS * FF;

    float* const hp0 = &HS[wid][0][0];
    float* const hp1 = &HS[wid][1][0];

    // ================= encoder =================
    for (int t = 0; t < SS; t++) {
        float* xc0 = &XS[wid][t & 1][0][0];
        float* xc1 = &XS[wid][t & 1][1][0];
        // build xin for own elem (each lane writes only its own data)
        {
            float* xc = e ? xc1 : xc0;
            if (j16 < 12) {
                xc[j16] = xq0;
            } else {
                const float* tb = etab + etb + oq0 * edim;
#pragma unroll
                for (int i = 0; i < 4; i++) xc[eoff + i] = tb[i];
                if (edim == 8) {
#pragma unroll
                    for (int i = 4; i < 8; i++) xc[eoff + i] = tb[i];
                }
            }
        }
        // rotate prefetch + issue t+3
        xq0 = xq1; xq1 = xq2; oq0 = oq1; oq1 = oq2;
        if (t + 3 < SS) {
            if (j16 < 12) { xq2 = xptr[0]; xptr += 12; }
            else          { oq2 = optr[0]; optr += 4; }
        }
        __syncwarp();
        // origin writes (coalesced readback)
#pragma unroll
        for (int rep = 0; rep < 3; rep++) {
            int i = lane + rep * 32;
            if (i < 72) {
                int e2 = (i >= 36);
                int f = i - 36 * e2;
                float v = (e2 ? xc1 : xc0)[f];
                (e2 ? origin1 : origin0)[(size_t)t * FF + f] = v;
            }
        }
        // matvec: both elems, split chains
        u64 aiA0[2] = {0, 0}, aiA1[2] = {0, 0}, aiB0[2] = {0, 0}, aiB1[2] = {0, 0};
        u64 ahA0[2] = {0, 0}, ahA1[2] = {0, 0}, ahB0[2] = {0, 0}, ahB1[2] = {0, 0};
        if (lane < 30) {
#pragma unroll
            for (int j = 0; j < 18; j++) {
                u64 x0k = *(const u64*)(xc0 + 2 * j);
                u64 x1k = *(const u64*)(xc1 + 2 * j);
                int h_ = j & 1;
                aiA0[h_] = ffma2(wiA[j], x0k, aiA0[h_]);
                aiB0[h_] = ffma2(wiB[j], x0k, aiB0[h_]);
                aiA1[h_] = ffma2(wiA[j], x1k, aiA1[h_]);
                aiB1[h_] = ffma2(wiB[j], x1k, aiB1[h_]);
            }
#pragma unroll
            for (int j = 0; j < 10; j++) {
                u64 h0k = *(const u64*)(hp0 + 2 * j);
                u64 h1k = *(const u64*)(hp1 + 2 * j);
                int h_ = j & 1;
                ahA0[h_] = ffma2(whA[j], h0k, ahA0[h_]);
                ahB0[h_] = ffma2(whB[j], h0k, ahB0[h_]);
                ahA1[h_] = ffma2(whA[j], h1k, ahA1[h_]);
                ahB1[h_] = ffma2(whB[j], h1k, ahB1[h_]);
            }
        }
        float giA0 = fold2(fadd2(aiA0[0], aiA0[1])) + biA;
        float giB0 = fold2(fadd2(aiB0[0], aiB0[1])) + biB;
        float ghA0 = fold2(fadd2(ahA0[0], ahA0[1])) + bhA;
        float ghB0 = fold2(fadd2(ahB0[0], ahB0[1])) + bhB;
        float giA1 = fold2(fadd2(aiA1[0], aiA1[1])) + biA;
        float giB1 = fold2(fadd2(aiB1[0], aiB1[1])) + biB;
        float ghA1 = fold2(fadd2(ahA1[0], ahA1[1])) + bhA;
        float ghB1 = fold2(fadd2(ahB1[0], ahB1[1])) + bhB;
        // n-gate exchange (all lanes execute shfls)
        float inA0 = __shfl_sync(0xffffffffu, giA0, nsrc);
        float inB0 = __shfl_sync(0xffffffffu, giB0, nsrc);
        float hnA0 = __shfl_sync(0xffffffffu, ghA0, nsrc);
        float hnB0 = __shfl_sync(0xffffffffu, ghB0, nsrc);
        float inA1 = __shfl_sync(0xffffffffu, giA1, nsrc);
        float inB1 = __shfl_sync(0xffffffffu, giB1, nsrc);
        float hnA1 = __shfl_sync(0xffffffffu, ghA1, nsrc);
        float hnB1 = __shfl_sync(0xffffffffu, ghB1, nsrc);
        if (lane < HH) {
            float in0 = nlo ? inA0 : inB0, hn0 = nlo ? hnA0 : hnB0;
            float in1 = nlo ? inA1 : inB1, hn1 = nlo ? hnA1 : hnB1;
            float r0 = sigf(giA0 + ghA0), z0 = sigf(giB0 + ghB0);
            float r1 = sigf(giA1 + ghA1), z1 = sigf(giB1 + ghB1);
            float n0 = tanhfast(fmaf(r0, hn0, in0));
            float n1 = tanhfast(fmaf(r1, hn1, in1));
            hreg0 = fmaf(z0, hreg0 - n0, n0);
            hreg1 = fmaf(z1, hreg1 - n1, n1);
            hp0[lane] = hreg0;
            hp1[lane] = hreg1;
        }
    }

    // ---- encoder->decoder handoff + weight reload ----
    if (lane < HH) {
        hreg0 = tanhfast(hreg0); hreg1 = tanhfast(hreg1);
        hp0[lane] = hreg0; hp1[lane] = hreg1;
    }
    if (lane < 30) {
        const u64* ra = (const u64*)(Wih2 + gA * FF);
        const u64* rb = (const u64*)(Wih2 + gB * FF);
#pragma unroll
        for (int j = 0; j < 18; j++) { wiA[j] = ra[j]; wiB[j] = rb[j]; }
        const u64* ha = (const u64*)(Whh2 + gA * HH);
        const u64* hb = (const u64*)(Whh2 + gB * HH);
#pragma unroll
        for (int j = 0; j < 10; j++) { whA[j] = ha[j]; whB[j] = hb[j]; }
        biA = bih2[gA]; biB = bih2[gB]; bhA = bhh2[gA]; bhB = bhh2[gB];
    }
    u64 wf0[10], wf1[10];
    float bf0 = 0.f, bf1 = 0.f;
    if (lane < 18) {
        const u64* f0 = (const u64*)(Wfc + (2 * lane) * HH);
        const u64* f1 = (const u64*)(Wfc + (2 * lane + 1) * HH);
#pragma unroll
        for (int j = 0; j < 10; j++) { wf0[j] = f0[j]; wf1[j] = f1[j]; }
        bf0 = bfc[2 * lane]; bf1 = bfc[2 * lane + 1];
    }

    float* const xb0 = &XS[wid][0][0][0];
    float* const xb1 = &XS[wid][0][1][0];

    // ================= decoder =================
    // t=0: FC only (x0 from h). t>0: GRU step + FC.
    for (int t = 0; t < SS; t++) {
        if (t > 0) {
            u64 aiA0[2] = {0, 0}, aiA1[2] = {0, 0}, aiB0[2] = {0, 0}, aiB1[2] = {0, 0};
            u64 ahA0[2] = {0, 0}, ahA1[2] = {0, 0}, ahB0[2] = {0, 0}, ahB1[2] = {0, 0};
            if (lane < 30) {
#pragma unroll
                for (int j = 0; j < 18; j++) {
                    u64 x0k = *(const u64*)(xb0 + 2 * j);
                    u64 x1k = *(const u64*)(xb1 + 2 * j);
                    int h_ = j & 1;
                    aiA0[h_] = ffma2(wiA[j], x0k, aiA0[h_]);
                    aiB0[h_] = ffma2(wiB[j], x0k, aiB0[h_]);
                    aiA1[h_] = ffma2(wiA[j], x1k, aiA1[h_]);
                    aiB1[h_] = ffma2(wiB[j], x1k, aiB1[h_]);
                }
#pragma unroll
                for (int j = 0; j < 10; j++) {
                    u64 h0k = *(const u64*)(hp0 + 2 * j);
                    u64 h1k = *(const u64*)(hp1 + 2 * j);
                    int h_ = j & 1;
                    ahA0[h_] = ffma2(whA[j], h0k, ahA0[h_]);
                    ahB0[h_] = ffma2(whB[j], h0k, ahB0[h_]);
                    ahA1[h_] = ffma2(whA[j], h1k, ahA1[h_]);
                    ahB1[h_] = ffma2(whB[j], h1k, ahB1[h_]);
                }
            }
            float giA0 = fold2(fadd2(aiA0[0], aiA0[1])) + biA;
            float giB0 = fold2(fadd2(aiB0[0], aiB0[1])) + biB;
            float ghA0 = fold2(fadd2(ahA0[0], ahA0[1])) + bhA;
            float ghB0 = fold2(fadd2(ahB0[0], ahB0[1])) + bhB;
            float giA1 = fold2(fadd2(aiA1[0], aiA1[1])) + biA;
            float giB1 = fold2(fadd2(aiB1[0], aiB1[1])) + biB;
            float ghA1 = fold2(fadd2(ahA1[0], ahA1[1])) + bhA;
            float ghB1 = fold2(fadd2(ahB1[0], ahB1[1])) + bhB;
            float inA0 = __shfl_sync(0xffffffffu, giA0, nsrc);
            float inB0 = __shfl_sync(0xffffffffu, giB0, nsrc);
            float hnA0 = __shfl_sync(0xffffffffu, ghA0, nsrc);
            float hnB0 = __shfl_sync(0xffffffffu, ghB0, nsrc);
            float inA1 = __shfl_sync(0xffffffffu, giA1, nsrc);
            float inB1 = __shfl_sync(0xffffffffu, giB1, nsrc);
            float hnA1 = __shfl_sync(0xffffffffu, ghA1, nsrc);
            float hnB1 = __shfl_sync(0xffffffffu, ghB1, nsrc);
            if (lane < HH) {
                float in0 = nlo ? inA0 : inB0, hn0 = nlo ? hnA0 : hnB0;
                float in1 = nlo ? inA1 : inB1, hn1 = nlo ? hnA1 : hnB1;
                float r0 = sigf(giA0 + ghA0), z0 = sigf(giB0 + ghB0);
                float r1 = sigf(giA1 + ghA1), z1 = sigf(giB1 + ghB1);
                float n0 = tanhfast(fmaf(r0, hn0, in0));
                float n1 = tanhfast(fmaf(r1, hn1, in1));
                hreg0 = tanhfast(fmaf(z0, hreg0 - n0, n0));
                hreg1 = tanhfast(fmaf(z1, hreg1 - n1, n1));
                hp0[lane] = hreg0;
                hp1[lane] = hreg1;
            }
        }
        __syncwarp();
        // FC: x = tanh(h @ Wfc^T + bfc); rows 2k,2k+1 per lane -> float2 stores
        if (lane < 18) {
            u64 a00 = 0, a01 = 0, a10 = 0, a11 = 0;
#pragma unroll
            for (int j = 0; j < 10; j++) {
                u64 h0k = *(const u64*)(hp0 + 2 * j);
                u64 h1k = *(const u64*)(hp1 + 2 * j);
                a00 = ffma2(wf0[j], h0k, a00);
                a01 = ffma2(wf1[j], h0k, a01);
                a10 = ffma2(wf0[j], h1k, a10);
                a11 = ffma2(wf1[j], h1k, a11);
            }
            float v00 = tanhfast(fold2(a00) + bf0);
            float v01 = tanhfast(fold2(a01) + bf1);
            float v10 = tanhfast(fold2(a10) + bf0);
            float v11 = tanhfast(fold2(a11) + bf1);
            *(float2*)(xb0 + 2 * lane) = make_float2(v00, v01);
            *(float2*)(xb1 + 2 * lane) = make_float2(v10, v11);
            size_t row = (size_t)(SS - 1 - t) * FF + 2 * lane;
            *(float2*)(xso0 + row) = make_float2(v00, v01);
            *(float2*)(xso1 + row) = make_float2(v10, v11);
        }
        __syncwarp();
    }
}

extern "C" void kernel_launch(void* const* d_in, const int* in_sizes, int n_in,
                              void* d_out, int out_size) {
    const float* x    = (const float*)d_in[0];
    const int*   oneh = (const int*)d_in[1];
    const float* e0   = (const float*)d_in[2];
    const float* e1   = (const float*)d_in[3];
    const float* e2   = (const float*)d_in[4];
    const float* e3   = (const float*)d_in[5];
    const float* Wih1 = (const float*)d_in[6];
    const float* Whh1 = (const float*)d_in[7];
    const float* bih1 = (const float*)d_in[8];
    const float* bhh1 = (const float*)d_in[9];
    const float* Wih2 = (const float*)d_in[10];
    const float* Whh2 = (const float*)d_in[11];
    const float* bih2 = (const float*)d_in[12];
    const float* bhh2 = (const float*)d_in[13];
    const float* Wfc  = (const float*)d_in[14];
    const float* bfc  = (const float*)d_in[15];

    gruae_kernel<<<BB / (2 * NWARPS), NTHREADS>>>(
        x, oneh, e0, e1, e2, e3, Wih1, Whh1, bih1, bhh1,
        Wih2, Whh2, bih2, bhh2, Wfc, bfc, (float*)d_out);
}